// round 2
// baseline (speedup 1.0000x reference)
#include <cuda_runtime.h>

#define THREADS 256
#define BLOCKS  1184   // 148 SMs * 8 blocks

__global__ void zero_out_kernel(float* out) {
    if (threadIdx.x == 0 && blockIdx.x == 0) out[0] = 0.0f;
}

__global__ __launch_bounds__(THREADS)
void loss_synonymy_kernel(const float4* __restrict__ s1,
                          const float4* __restrict__ s2,
                          const float*  __restrict__ score,
                          float* __restrict__ out,
                          int B)
{
    const int lane   = threadIdx.x & 31;
    const int warp   = (blockIdx.x * THREADS + threadIdx.x) >> 5;
    const int nwarps = (gridDim.x * THREADS) >> 5;

    float acc = 0.0f;

    for (int row = warp; row < B; row += nwarps) {
        const long base = (long)row * 32;  // 32 float4 per row (D=128)
        float4 a = __ldg(&s1[base + lane]);
        float4 b = __ldg(&s2[base + lane]);

        float dx = a.x - b.x;
        float dy = a.y - b.y;
        float dz = a.z - b.z;
        float dw = a.w - b.w;
        float ss = dx*dx + dy*dy + dz*dz + dw*dw;

        // warp all-reduce of sum of squares
        #pragma unroll
        for (int off = 16; off > 0; off >>= 1)
            ss += __shfl_xor_sync(0xffffffffu, ss, off);

        float t = tanhf(sqrtf(ss));
        float sc = __ldg(&score[row]);          // broadcast (same addr all lanes)
        float e = (sc >= 0.6f) ? (1.0f - t) : (1.0f + t);
        acc += fmaxf(e, 0.0f);
    }

    // acc is identical across all lanes of a warp (post all-reduce math);
    // keep only lane 0's copy.
    __shared__ float warp_sums[THREADS / 32];
    if (lane == 0) warp_sums[threadIdx.x >> 5] = acc;
    __syncthreads();

    if (threadIdx.x < THREADS / 32) {
        float v = warp_sums[threadIdx.x];
        #pragma unroll
        for (int off = (THREADS / 64); off > 0; off >>= 1)
            v += __shfl_xor_sync(0xffu, v, off);
        if (threadIdx.x == 0) atomicAdd(out, v);
    }
}

extern "C" void kernel_launch(void* const* d_in, const int* in_sizes, int n_in,
                              void* d_out, int out_size)
{
    const float4* s1    = (const float4*)d_in[0];
    const float4* s2    = (const float4*)d_in[1];
    const float*  score = (const float*)d_in[2];
    float* out = (float*)d_out;

    const int B = in_sizes[2];  // synonymy_score has B elements

    zero_out_kernel<<<1, 32>>>(out);
    loss_synonymy_kernel<<<BLOCKS, THREADS>>>(s1, s2, score, out, B);
}